// round 16
// baseline (speedup 1.0000x reference)
#include <cuda_runtime.h>
#include <cuda_fp16.h>
#include <cstdint>

#define N_NODES 50000
#define N_REL 8
#define N_EDGE 64000
#define D 128

#define A_RB 272                      // bytes per fp16 A row in smem (16B mult)
#define A_BYTES (128 * A_RB)          // 34816 per tile buffer
#define B_OFF (2 * A_BYTES)           // 69632
#define B_BYTES 32768                 // packed fp16 W image
#define MB_OFF (B_OFF + B_BYTES)      // 102400: mbA0|mbA1|mbB
#define SDST_OFF (MB_OFF + 32)        // 256 ints
#define SEW_OFF (SDST_OFF + 1024)     // 256 floats
#define EDGE_SMEM (SEW_OFF + 1024)    // 104480 B -> 2 CTAs/SM

#define RMB_OFF (A_BYTES + B_BYTES)   // root: A(34816)+B(32768)
#define ROOT_SMEM (RMB_OFF + 16)

// fp16 images (static device scratch)
__device__ __align__(256) __half g_xh[N_NODES * D];
__device__ __align__(128) __half g_wth[N_REL * D * D];
__device__ __align__(128) __half g_rwh[D * D];

#define MBAR_INIT(mb, c) asm volatile("mbarrier.init.shared.b64 [%0], %1;" ::"r"(mb), "r"(c) : "memory")
#define MBAR_EXPECT(mb, bytes) asm volatile("mbarrier.arrive.expect_tx.shared.b64 _, [%0], %1;" ::"r"(mb), "r"(bytes) : "memory")

__device__ __forceinline__ void bulk_cp(uint32_t dst, const void* src, uint32_t bytes, uint32_t mb) {
    asm volatile(
        "cp.async.bulk.shared::cta.global.mbarrier::complete_tx::bytes [%0], [%1], %2, [%3];"
        ::"r"(dst), "l"(src), "r"(bytes), "r"(mb) : "memory");
}

// Bounded parity wait: protocol bug -> fast wrong answer, never a hung container.
__device__ __forceinline__ void mbar_wait(uint32_t mb, uint32_t parity) {
    for (int i = 0; i < (1 << 21); i++) {
        uint32_t done;
        asm volatile(
            "{\n\t.reg .pred p;\n\t"
            "mbarrier.try_wait.parity.acquire.cta.shared::cta.b64 p, [%1], %2;\n\t"
            "selp.b32 %0, 1, 0, p;\n\t}"
            : "=r"(done) : "r"(mb), "r"(parity) : "memory");
        if (done) return;
    }
}

__device__ __forceinline__ void mma_f16(float c[4], const uint32_t a[4],
                                        uint32_t b0, uint32_t b1) {
    asm volatile(
        "mma.sync.aligned.m16n8k16.row.col.f32.f16.f16.f32 "
        "{%0,%1,%2,%3}, {%4,%5,%6,%7}, {%8,%9}, {%0,%1,%2,%3};\n"
        : "+f"(c[0]), "+f"(c[1]), "+f"(c[2]), "+f"(c[3])
        : "r"(a[0]), "r"(a[1]), "r"(a[2]), "r"(a[3]), "r"(b0), "r"(b1));
}

// ---------------------------------------------------------------------------
// x -> fp16 conversion
// ---------------------------------------------------------------------------
__device__ __forceinline__ uint32_t f2h2(float a, float b) {
    __half2 h = __floats2half2_rn(a, b);
    return *(uint32_t*)&h;
}

extern "C" __global__ void xconv_kernel(const float4* __restrict__ x) {
    int i = blockIdx.x * blockDim.x + threadIdx.x;
    const int n8 = N_NODES * D / 8;
    if (i < n8) {
        float4 a = x[2 * i], b = x[2 * i + 1];
        uint4 u;
        u.x = f2h2(a.x, a.y);
        u.y = f2h2(a.z, a.w);
        u.z = f2h2(b.x, b.y);
        u.w = f2h2(b.z, b.w);
        *(uint4*)&g_xh[i * 8] = u;
    }
}

// ---------------------------------------------------------------------------
// W pack: fragment-order fp16 image (same as R13/R14)
// ---------------------------------------------------------------------------
__device__ __forceinline__ int pack_half_idx(int k, int n) {
    int s = k >> 4, kl = k & 15, r = kl >> 3, tg = (kl >> 1) & 3, hi = kl & 1;
    int nw = n >> 6, j = (n & 63) >> 3, g = n & 7;
    int lane = g * 4 + tg, f = 2 * j + r;
    int u = lane * 4 + (f >> 2);
    int cp = (u & ~7) | ((u & 7) ^ ((u >> 3) & 7));
    return (s * 1024 + nw * 512 + cp * 4 + (f & 3)) * 2 + hi;
}

extern "C" __global__ void pack_w_kernel(const float* __restrict__ weight,
                                         const float* __restrict__ root_w) {
    int r = blockIdx.x;
    if (r < N_REL) {
        for (int i = threadIdx.x; i < D * D; i += blockDim.x) {
            int k = i >> 7, n = i & 127;
            g_wth[r * D * D + pack_half_idx(k, n)] = __float2half_rn(weight[r * D * D + i]);
        }
    } else {
        for (int i = threadIdx.x; i < D * D; i += blockDim.x) {
            int k = i >> 7, n = i & 127;
            g_rwh[pack_half_idx(k, n)] = __float2half_rn(root_w[i]);
        }
    }
}

__device__ __forceinline__ void make_boff(int lane, int boff[4]) {
    int lh = lane >> 1, sel = (lane & 1) * 4, x7 = lh & 7;
#pragma unroll
    for (int j = 0; j < 4; j++) boff[j] = (lh * 8 + ((sel + j) ^ x7)) * 4;
}

// full K=128 mainloop: 8 fp16 k16-steps
__device__ __forceinline__ void compute_tile(const char* __restrict__ As,
                                             const uint32_t* __restrict__ Bu,
                                             int g, int tg, int mw, int nw,
                                             const int boff[4],
                                             float acc[2][8][4]) {
#pragma unroll
    for (int s = 0; s < 8; s++) {
        uint32_t a[2][4];
#pragma unroll
        for (int mi = 0; mi < 2; mi++) {
            const char* Ar = As + (mw * 32 + mi * 16 + g) * A_RB + s * 32 + tg * 4;
            a[mi][0] = *(const uint32_t*)Ar;
            a[mi][1] = *(const uint32_t*)(Ar + 8 * A_RB);
            a[mi][2] = *(const uint32_t*)(Ar + 16);
            a[mi][3] = *(const uint32_t*)(Ar + 8 * A_RB + 16);
        }
        uint32_t bf[16];
        const uint32_t* Bk = Bu + s * 1024 + nw * 512;
#pragma unroll
        for (int j4 = 0; j4 < 4; j4++) {
            uint4 v = *(const uint4*)(Bk + boff[j4]);
            bf[4 * j4 + 0] = v.x;
            bf[4 * j4 + 1] = v.y;
            bf[4 * j4 + 2] = v.z;
            bf[4 * j4 + 3] = v.w;
        }
#pragma unroll
        for (int mi = 0; mi < 2; mi++)
#pragma unroll
            for (int j = 0; j < 8; j++)
                mma_f16(acc[mi][j], a[mi], bf[2 * j], bf[2 * j + 1]);
    }
}

// ---------------------------------------------------------------------------
// Kernel: root = x @ root_w + root_b + bias (dense init) — unchanged
// ---------------------------------------------------------------------------
extern "C" __global__ void __launch_bounds__(256, 2)
root_kernel(const float* __restrict__ root_b, const float* __restrict__ bias,
            float* __restrict__ out) {
    extern __shared__ char smem[];
    const uint32_t sb = (uint32_t)__cvta_generic_to_shared(smem);
    const char* As = smem;
    const uint32_t* Bu = (const uint32_t*)(smem + A_BYTES);
    const uint32_t mbA = sb + RMB_OFF, mbB = mbA + 8;

    const int tid = threadIdx.x;
    const int n0 = blockIdx.x * 128;

    if (tid == 0) { MBAR_INIT(mbA, 1); MBAR_INIT(mbB, 1); }
    __syncthreads();
    if (tid == 0) {
        MBAR_EXPECT(mbA, 128 * 256);
        MBAR_EXPECT(mbB, B_BYTES);
        bulk_cp(sb + A_BYTES, g_rwh, B_BYTES, mbB);
    }
    if (tid < 128) {
        int gr = n0 + tid;
        if (gr >= N_NODES) gr = 0;
        bulk_cp(sb + tid * A_RB, g_xh + (size_t)gr * D, 256, mbA);
    }

    const int lane = tid & 31, warp = tid >> 5;
    const int g = lane >> 2, tg = lane & 3;
    const int mw = warp >> 1, nw = warp & 1;
    int boff[4];
    make_boff(lane, boff);

    float acc[2][8][4];
#pragma unroll
    for (int mi = 0; mi < 2; mi++)
#pragma unroll
        for (int j = 0; j < 8; j++)
#pragma unroll
            for (int c4 = 0; c4 < 4; c4++) acc[mi][j][c4] = 0.f;

    mbar_wait(mbA, 0);
    mbar_wait(mbB, 0);
    compute_tile(As, Bu, g, tg, mw, nw, boff, acc);

#pragma unroll
    for (int mi = 0; mi < 2; mi++) {
        int row0 = n0 + mw * 32 + mi * 16 + g;
#pragma unroll
        for (int j = 0; j < 8; j++) {
            int col = nw * 64 + 8 * j + 2 * tg;
            float b0 = root_b[col] + bias[col];
            float b1 = root_b[col + 1] + bias[col + 1];
            if (row0 < N_NODES)
                *(float2*)&out[(size_t)row0 * D + col] =
                    make_float2(acc[mi][j][0] + b0, acc[mi][j][1] + b1);
            if (row0 + 8 < N_NODES)
                *(float2*)&out[(size_t)(row0 + 8) * D + col] =
                    make_float2(acc[mi][j][2] + b0, acc[mi][j][3] + b1);
        }
    }
}

// ---------------------------------------------------------------------------
// Kernel: edge — 2 tiles/CTA pipelined; fp16 full-tile C staging (stride 272,
// conflict-free), cvt->fp32 red.v4 scatter; scatter(t) overlaps compute(t+1).
// ---------------------------------------------------------------------------
extern "C" __global__ void __launch_bounds__(256, 2)
edge_kernel(const int* __restrict__ src, const int* __restrict__ dst,
            const float* __restrict__ ew, float* __restrict__ out) {
    extern __shared__ char smem[];
    const uint32_t sb = (uint32_t)__cvta_generic_to_shared(smem);
    const uint32_t mbA0 = sb + MB_OFF, mbA1 = mbA0 + 8, mbB = mbA0 + 16;
    int* s_dst = (int*)(smem + SDST_OFF);
    float* s_ew = (float*)(smem + SEW_OFF);

    const int tid = threadIdx.x;
    const int r = blockIdx.y;
    const int ebase = r * N_EDGE + blockIdx.x * 256;

    if (tid == 0) { MBAR_INIT(mbA0, 1); MBAR_INIT(mbA1, 1); MBAR_INIT(mbB, 1); }
    __syncthreads();
    if (tid == 0) {
        MBAR_EXPECT(mbA0, 128 * 256);
        MBAR_EXPECT(mbA1, 128 * 256);
        MBAR_EXPECT(mbB, B_BYTES);
        bulk_cp(sb + B_OFF, g_wth + (size_t)r * D * D, B_BYTES, mbB);
    }
    {
        int srow = __ldg(&src[ebase + tid]);
        int tt = tid >> 7, lrow = tid & 127;
        bulk_cp(sb + tt * A_BYTES + lrow * A_RB, g_xh + (size_t)srow * D, 256,
                tt ? mbA1 : mbA0);
        s_dst[tid] = __ldg(&dst[ebase + tid]);
        s_ew[tid] = __ldg(&ew[ebase + tid]);
    }

    const int lane = tid & 31, warp = tid >> 5;
    const int g = lane >> 2, tg = lane & 3;
    const int mw = warp >> 1, nw = warp & 1;
    int boff[4];
    make_boff(lane, boff);
    const uint32_t* Bu = (const uint32_t*)(smem + B_OFF);

#pragma unroll
    for (int t = 0; t < 2; t++) {
        float acc[2][8][4];
#pragma unroll
        for (int mi = 0; mi < 2; mi++)
#pragma unroll
            for (int j = 0; j < 8; j++)
#pragma unroll
                for (int c4 = 0; c4 < 4; c4++) acc[mi][j][c4] = 0.f;

        mbar_wait(t ? mbA1 : mbA0, 0);
        if (t == 0) mbar_wait(mbB, 0);
        compute_tile(smem + t * A_BYTES, Bu, g, tg, mw, nw, boff, acc);

        __syncthreads();  // all warps done reading A(t); s_dst/s_ew visible

        // stage C*ew as fp16 over the dead A buffer (row stride A_RB=272B,
        // conflict-free for STS.32 staging and LDS.128 scatter reads)
        char* Cs2 = smem + t * A_BYTES;
#pragma unroll
        for (int mi = 0; mi < 2; mi++) {
            int lrow = mw * 32 + mi * 16 + g;
            float w0 = s_ew[t * 128 + lrow], w1 = s_ew[t * 128 + lrow + 8];
#pragma unroll
            for (int j = 0; j < 8; j++) {
                int col = nw * 64 + 8 * j + 2 * tg;
                *(__half2*)(Cs2 + lrow * A_RB + col * 2) =
                    __floats2half2_rn(acc[mi][j][0] * w0, acc[mi][j][1] * w0);
                *(__half2*)(Cs2 + (lrow + 8) * A_RB + col * 2) =
                    __floats2half2_rn(acc[mi][j][2] * w1, acc[mi][j][3] * w1);
            }
        }
        __syncthreads();  // staging visible

        // scatter: 8 iters x (LDS.128 -> 8 halves -> fp32 -> 2x red.v4)
#pragma unroll
        for (int it = 0; it < 8; it++) {
            int s2 = tid + it * 256;
            int row = s2 >> 4, c16 = s2 & 15;
            uint4 v = *(const uint4*)(Cs2 + row * A_RB + c16 * 16);
            float2 f0 = __half22float2(*(__half2*)&v.x);
            float2 f1 = __half22float2(*(__half2*)&v.y);
            float2 f2 = __half22float2(*(__half2*)&v.z);
            float2 f3 = __half22float2(*(__half2*)&v.w);
            int d = s_dst[t * 128 + row];
            float* p = out + (size_t)d * D + c16 * 8;
            asm volatile("red.global.add.v4.f32 [%0], {%1,%2,%3,%4};"
                         ::"l"(p), "f"(f0.x), "f"(f0.y), "f"(f1.x), "f"(f1.y)
                         : "memory");
            asm volatile("red.global.add.v4.f32 [%0], {%1,%2,%3,%4};"
                         ::"l"(p + 4), "f"(f2.x), "f"(f2.y), "f"(f3.x), "f"(f3.y)
                         : "memory");
        }
        // no sync: scatter(t) drains while compute(t+1) runs (disjoint smem)
    }
}

// ---------------------------------------------------------------------------
// ReLU
// ---------------------------------------------------------------------------
extern "C" __global__ void relu_kernel(float4* __restrict__ out, int n4) {
    int i = blockIdx.x * blockDim.x + threadIdx.x;
    int stride = gridDim.x * blockDim.x;
    for (; i < n4; i += stride) {
        float4 v = out[i];
        v.x = fmaxf(v.x, 0.f);
        v.y = fmaxf(v.y, 0.f);
        v.z = fmaxf(v.z, 0.f);
        v.w = fmaxf(v.w, 0.f);
        out[i] = v;
    }
}

extern "C" void kernel_launch(void* const* d_in, const int* in_sizes, int n_in,
                              void* d_out, int out_size) {
    const float* x      = (const float*)d_in[0];
    const int*   src    = (const int*)d_in[1];
    const int*   dst    = (const int*)d_in[2];
    const float* ew     = (const float*)d_in[3];
    const float* weight = (const float*)d_in[4];
    const float* root_w = (const float*)d_in[5];
    const float* root_b = (const float*)d_in[6];
    const float* bias   = (const float*)d_in[7];
    float* out = (float*)d_out;

    cudaFuncSetAttribute(root_kernel, cudaFuncAttributeMaxDynamicSharedMemorySize, ROOT_SMEM);
    cudaFuncSetAttribute(edge_kernel, cudaFuncAttributeMaxDynamicSharedMemorySize, EDGE_SMEM);

    int n8 = N_NODES * D / 8;
    xconv_kernel<<<(n8 + 255) / 256, 256>>>((const float4*)x);
    pack_w_kernel<<<N_REL + 1, 256>>>(weight, root_w);

    int root_blocks = (N_NODES + 127) / 128;  // 391
    root_kernel<<<root_blocks, 256, ROOT_SMEM>>>(root_b, bias, out);

    dim3 egrid(N_EDGE / 256, N_REL);  // 250 x 8 = 2000 CTAs
    edge_kernel<<<egrid, 256, EDGE_SMEM>>>(src, dst, ew, out);

    int n4 = out_size / 4;
    relu_kernel<<<1184, 256>>>((float4*)out, n4);
}

// round 17
// speedup vs baseline: 1.0027x; 1.0027x over previous
#include <cuda_runtime.h>
#include <cuda_fp16.h>
#include <cstdint>

#define N_NODES 50000
#define N_REL 8
#define N_EDGE 64000
#define D 128

#define A_RB 272                      // bytes per fp16 A row in smem (16B mult)
#define A_BYTES (128 * A_RB)          // 34816 per tile buffer
#define B_OFF (2 * A_BYTES)           // 69632
#define B_BYTES 32768                 // packed fp16 W image
#define MB_OFF (B_OFF + B_BYTES)      // 102400: mbA0|mbA1|mbB
#define SDST_OFF (MB_OFF + 32)        // 256 ints
#define SEW_OFF (SDST_OFF + 1024)     // 256 floats
#define EDGE_SMEM (SEW_OFF + 1024)    // 104480 B -> 2 CTAs/SM

#define RMB_OFF (A_BYTES + B_BYTES)   // root: A(34816)+B(32768)
#define ROOT_SMEM (RMB_OFF + 16)

// fp16 images (static device scratch)
__device__ __align__(256) __half g_xh[N_NODES * D];
__device__ __align__(128) __half g_wth[N_REL * D * D];
__device__ __align__(128) __half g_rwh[D * D];

#define MBAR_INIT(mb, c) asm volatile("mbarrier.init.shared.b64 [%0], %1;" ::"r"(mb), "r"(c) : "memory")
#define MBAR_EXPECT(mb, bytes) asm volatile("mbarrier.arrive.expect_tx.shared.b64 _, [%0], %1;" ::"r"(mb), "r"(bytes) : "memory")

__device__ __forceinline__ void bulk_cp(uint32_t dst, const void* src, uint32_t bytes, uint32_t mb) {
    asm volatile(
        "cp.async.bulk.shared::cta.global.mbarrier::complete_tx::bytes [%0], [%1], %2, [%3];"
        ::"r"(dst), "l"(src), "r"(bytes), "r"(mb) : "memory");
}

// Bounded parity wait: protocol bug -> fast wrong answer, never a hung container.
__device__ __forceinline__ void mbar_wait(uint32_t mb, uint32_t parity) {
    for (int i = 0; i < (1 << 21); i++) {
        uint32_t done;
        asm volatile(
            "{\n\t.reg .pred p;\n\t"
            "mbarrier.try_wait.parity.acquire.cta.shared::cta.b64 p, [%1], %2;\n\t"
            "selp.b32 %0, 1, 0, p;\n\t}"
            : "=r"(done) : "r"(mb), "r"(parity) : "memory");
        if (done) return;
    }
}

__device__ __forceinline__ void mma_f16(float c[4], const uint32_t a[4],
                                        uint32_t b0, uint32_t b1) {
    asm volatile(
        "mma.sync.aligned.m16n8k16.row.col.f32.f16.f16.f32 "
        "{%0,%1,%2,%3}, {%4,%5,%6,%7}, {%8,%9}, {%0,%1,%2,%3};\n"
        : "+f"(c[0]), "+f"(c[1]), "+f"(c[2]), "+f"(c[3])
        : "r"(a[0]), "r"(a[1]), "r"(a[2]), "r"(a[3]), "r"(b0), "r"(b1));
}

// ---------------------------------------------------------------------------
// x -> fp16 conversion
// ---------------------------------------------------------------------------
__device__ __forceinline__ uint32_t f2h2(float a, float b) {
    __half2 h = __floats2half2_rn(a, b);
    return *(uint32_t*)&h;
}

extern "C" __global__ void xconv_kernel(const float4* __restrict__ x) {
    int i = blockIdx.x * blockDim.x + threadIdx.x;
    const int n8 = N_NODES * D / 8;
    if (i < n8) {
        float4 a = x[2 * i], b = x[2 * i + 1];
        uint4 u;
        u.x = f2h2(a.x, a.y);
        u.y = f2h2(a.z, a.w);
        u.z = f2h2(b.x, b.y);
        u.w = f2h2(b.z, b.w);
        *(uint4*)&g_xh[i * 8] = u;
    }
}

// ---------------------------------------------------------------------------
// W pack: fragment-order fp16 image (same as R13/R14)
// ---------------------------------------------------------------------------
__device__ __forceinline__ int pack_half_idx(int k, int n) {
    int s = k >> 4, kl = k & 15, r = kl >> 3, tg = (kl >> 1) & 3, hi = kl & 1;
    int nw = n >> 6, j = (n & 63) >> 3, g = n & 7;
    int lane = g * 4 + tg, f = 2 * j + r;
    int u = lane * 4 + (f >> 2);
    int cp = (u & ~7) | ((u & 7) ^ ((u >> 3) & 7));
    return (s * 1024 + nw * 512 + cp * 4 + (f & 3)) * 2 + hi;
}

extern "C" __global__ void pack_w_kernel(const float* __restrict__ weight,
                                         const float* __restrict__ root_w) {
    int r = blockIdx.x;
    if (r < N_REL) {
        for (int i = threadIdx.x; i < D * D; i += blockDim.x) {
            int k = i >> 7, n = i & 127;
            g_wth[r * D * D + pack_half_idx(k, n)] = __float2half_rn(weight[r * D * D + i]);
        }
    } else {
        for (int i = threadIdx.x; i < D * D; i += blockDim.x) {
            int k = i >> 7, n = i & 127;
            g_rwh[pack_half_idx(k, n)] = __float2half_rn(root_w[i]);
        }
    }
}

__device__ __forceinline__ void make_boff(int lane, int boff[4]) {
    int lh = lane >> 1, sel = (lane & 1) * 4, x7 = lh & 7;
#pragma unroll
    for (int j = 0; j < 4; j++) boff[j] = (lh * 8 + ((sel + j) ^ x7)) * 4;
}

// full K=128 mainloop: 8 fp16 k16-steps
__device__ __forceinline__ void compute_tile(const char* __restrict__ As,
                                             const uint32_t* __restrict__ Bu,
                                             int g, int tg, int mw, int nw,
                                             const int boff[4],
                                             float acc[2][8][4]) {
#pragma unroll
    for (int s = 0; s < 8; s++) {
        uint32_t a[2][4];
#pragma unroll
        for (int mi = 0; mi < 2; mi++) {
            const char* Ar = As + (mw * 32 + mi * 16 + g) * A_RB + s * 32 + tg * 4;
            a[mi][0] = *(const uint32_t*)Ar;
            a[mi][1] = *(const uint32_t*)(Ar + 8 * A_RB);
            a[mi][2] = *(const uint32_t*)(Ar + 16);
            a[mi][3] = *(const uint32_t*)(Ar + 8 * A_RB + 16);
        }
        uint32_t bf[16];
        const uint32_t* Bk = Bu + s * 1024 + nw * 512;
#pragma unroll
        for (int j4 = 0; j4 < 4; j4++) {
            uint4 v = *(const uint4*)(Bk + boff[j4]);
            bf[4 * j4 + 0] = v.x;
            bf[4 * j4 + 1] = v.y;
            bf[4 * j4 + 2] = v.z;
            bf[4 * j4 + 3] = v.w;
        }
#pragma unroll
        for (int mi = 0; mi < 2; mi++)
#pragma unroll
            for (int j = 0; j < 8; j++)
                mma_f16(acc[mi][j], a[mi], bf[2 * j], bf[2 * j + 1]);
    }
}

// ---------------------------------------------------------------------------
// Kernel: root = x @ root_w + root_b + bias (dense init) — unchanged
// ---------------------------------------------------------------------------
extern "C" __global__ void __launch_bounds__(256, 2)
root_kernel(const float* __restrict__ root_b, const float* __restrict__ bias,
            float* __restrict__ out) {
    extern __shared__ char smem[];
    const uint32_t sb = (uint32_t)__cvta_generic_to_shared(smem);
    const char* As = smem;
    const uint32_t* Bu = (const uint32_t*)(smem + A_BYTES);
    const uint32_t mbA = sb + RMB_OFF, mbB = mbA + 8;

    const int tid = threadIdx.x;
    const int n0 = blockIdx.x * 128;

    if (tid == 0) { MBAR_INIT(mbA, 1); MBAR_INIT(mbB, 1); }
    __syncthreads();
    if (tid == 0) {
        MBAR_EXPECT(mbA, 128 * 256);
        MBAR_EXPECT(mbB, B_BYTES);
        bulk_cp(sb + A_BYTES, g_rwh, B_BYTES, mbB);
    }
    if (tid < 128) {
        int gr = n0 + tid;
        if (gr >= N_NODES) gr = 0;
        bulk_cp(sb + tid * A_RB, g_xh + (size_t)gr * D, 256, mbA);
    }

    const int lane = tid & 31, warp = tid >> 5;
    const int g = lane >> 2, tg = lane & 3;
    const int mw = warp >> 1, nw = warp & 1;
    int boff[4];
    make_boff(lane, boff);

    float acc[2][8][4];
#pragma unroll
    for (int mi = 0; mi < 2; mi++)
#pragma unroll
        for (int j = 0; j < 8; j++)
#pragma unroll
            for (int c4 = 0; c4 < 4; c4++) acc[mi][j][c4] = 0.f;

    mbar_wait(mbA, 0);
    mbar_wait(mbB, 0);
    compute_tile(As, Bu, g, tg, mw, nw, boff, acc);

#pragma unroll
    for (int mi = 0; mi < 2; mi++) {
        int row0 = n0 + mw * 32 + mi * 16 + g;
#pragma unroll
        for (int j = 0; j < 8; j++) {
            int col = nw * 64 + 8 * j + 2 * tg;
            float b0 = root_b[col] + bias[col];
            float b1 = root_b[col + 1] + bias[col + 1];
            if (row0 < N_NODES)
                *(float2*)&out[(size_t)row0 * D + col] =
                    make_float2(acc[mi][j][0] + b0, acc[mi][j][1] + b1);
            if (row0 + 8 < N_NODES)
                *(float2*)&out[(size_t)(row0 + 8) * D + col] =
                    make_float2(acc[mi][j][2] + b0, acc[mi][j][3] + b1);
        }
    }
}

// ---------------------------------------------------------------------------
// Kernel: edge — 2 tiles/CTA pipelined; fp16 full-tile C staging (stride 272,
// conflict-free), cvt->fp32 red.v4 scatter; scatter(t) overlaps compute(t+1).
// ---------------------------------------------------------------------------
extern "C" __global__ void __launch_bounds__(256, 2)
edge_kernel(const int* __restrict__ src, const int* __restrict__ dst,
            const float* __restrict__ ew, float* __restrict__ out) {
    extern __shared__ char smem[];
    const uint32_t sb = (uint32_t)__cvta_generic_to_shared(smem);
    const uint32_t mbA0 = sb + MB_OFF, mbA1 = mbA0 + 8, mbB = mbA0 + 16;
    int* s_dst = (int*)(smem + SDST_OFF);
    float* s_ew = (float*)(smem + SEW_OFF);

    const int tid = threadIdx.x;
    const int r = blockIdx.y;
    const int ebase = r * N_EDGE + blockIdx.x * 256;

    if (tid == 0) { MBAR_INIT(mbA0, 1); MBAR_INIT(mbA1, 1); MBAR_INIT(mbB, 1); }
    __syncthreads();
    if (tid == 0) {
        MBAR_EXPECT(mbA0, 128 * 256);
        MBAR_EXPECT(mbA1, 128 * 256);
        MBAR_EXPECT(mbB, B_BYTES);
        bulk_cp(sb + B_OFF, g_wth + (size_t)r * D * D, B_BYTES, mbB);
    }
    {
        int srow = __ldg(&src[ebase + tid]);
        int tt = tid >> 7, lrow = tid & 127;
        bulk_cp(sb + tt * A_BYTES + lrow * A_RB, g_xh + (size_t)srow * D, 256,
                tt ? mbA1 : mbA0);
        s_dst[tid] = __ldg(&dst[ebase + tid]);
        s_ew[tid] = __ldg(&ew[ebase + tid]);
    }

    const int lane = tid & 31, warp = tid >> 5;
    const int g = lane >> 2, tg = lane & 3;
    const int mw = warp >> 1, nw = warp & 1;
    int boff[4];
    make_boff(lane, boff);
    const uint32_t* Bu = (const uint32_t*)(smem + B_OFF);

#pragma unroll
    for (int t = 0; t < 2; t++) {
        float acc[2][8][4];
#pragma unroll
        for (int mi = 0; mi < 2; mi++)
#pragma unroll
            for (int j = 0; j < 8; j++)
#pragma unroll
                for (int c4 = 0; c4 < 4; c4++) acc[mi][j][c4] = 0.f;

        mbar_wait(t ? mbA1 : mbA0, 0);
        if (t == 0) mbar_wait(mbB, 0);
        compute_tile(smem + t * A_BYTES, Bu, g, tg, mw, nw, boff, acc);

        __syncthreads();  // all warps done reading A(t); s_dst/s_ew visible

        // stage C*ew as fp16 over the dead A buffer (row stride A_RB=272B,
        // conflict-free for STS.32 staging and LDS.128 scatter reads)
        char* Cs2 = smem + t * A_BYTES;
#pragma unroll
        for (int mi = 0; mi < 2; mi++) {
            int lrow = mw * 32 + mi * 16 + g;
            float w0 = s_ew[t * 128 + lrow], w1 = s_ew[t * 128 + lrow + 8];
#pragma unroll
            for (int j = 0; j < 8; j++) {
                int col = nw * 64 + 8 * j + 2 * tg;
                *(__half2*)(Cs2 + lrow * A_RB + col * 2) =
                    __floats2half2_rn(acc[mi][j][0] * w0, acc[mi][j][1] * w0);
                *(__half2*)(Cs2 + (lrow + 8) * A_RB + col * 2) =
                    __floats2half2_rn(acc[mi][j][2] * w1, acc[mi][j][3] * w1);
            }
        }
        __syncthreads();  // staging visible

        // scatter: 8 iters x (LDS.128 -> 8 halves -> fp32 -> 2x red.v4)
#pragma unroll
        for (int it = 0; it < 8; it++) {
            int s2 = tid + it * 256;
            int row = s2 >> 4, c16 = s2 & 15;
            uint4 v = *(const uint4*)(Cs2 + row * A_RB + c16 * 16);
            float2 f0 = __half22float2(*(__half2*)&v.x);
            float2 f1 = __half22float2(*(__half2*)&v.y);
            float2 f2 = __half22float2(*(__half2*)&v.z);
            float2 f3 = __half22float2(*(__half2*)&v.w);
            int d = s_dst[t * 128 + row];
            float* p = out + (size_t)d * D + c16 * 8;
            asm volatile("red.global.add.v4.f32 [%0], {%1,%2,%3,%4};"
                         ::"l"(p), "f"(f0.x), "f"(f0.y), "f"(f1.x), "f"(f1.y)
                         : "memory");
            asm volatile("red.global.add.v4.f32 [%0], {%1,%2,%3,%4};"
                         ::"l"(p + 4), "f"(f2.x), "f"(f2.y), "f"(f3.x), "f"(f3.y)
                         : "memory");
        }
        // no sync: scatter(t) drains while compute(t+1) runs (disjoint smem)
    }
}

// ---------------------------------------------------------------------------
// ReLU
// ---------------------------------------------------------------------------
extern "C" __global__ void relu_kernel(float4* __restrict__ out, int n4) {
    int i = blockIdx.x * blockDim.x + threadIdx.x;
    int stride = gridDim.x * blockDim.x;
    for (; i < n4; i += stride) {
        float4 v = out[i];
        v.x = fmaxf(v.x, 0.f);
        v.y = fmaxf(v.y, 0.f);
        v.z = fmaxf(v.z, 0.f);
        v.w = fmaxf(v.w, 0.f);
        out[i] = v;
    }
}

extern "C" void kernel_launch(void* const* d_in, const int* in_sizes, int n_in,
                              void* d_out, int out_size) {
    const float* x      = (const float*)d_in[0];
    const int*   src    = (const int*)d_in[1];
    const int*   dst    = (const int*)d_in[2];
    const float* ew     = (const float*)d_in[3];
    const float* weight = (const float*)d_in[4];
    const float* root_w = (const float*)d_in[5];
    const float* root_b = (const float*)d_in[6];
    const float* bias   = (const float*)d_in[7];
    float* out = (float*)d_out;

    cudaFuncSetAttribute(root_kernel, cudaFuncAttributeMaxDynamicSharedMemorySize, ROOT_SMEM);
    cudaFuncSetAttribute(edge_kernel, cudaFuncAttributeMaxDynamicSharedMemorySize, EDGE_SMEM);

    int n8 = N_NODES * D / 8;
    xconv_kernel<<<(n8 + 255) / 256, 256>>>((const float4*)x);
    pack_w_kernel<<<N_REL + 1, 256>>>(weight, root_w);

    int root_blocks = (N_NODES + 127) / 128;  // 391
    root_kernel<<<root_blocks, 256, ROOT_SMEM>>>(root_b, bias, out);

    dim3 egrid(N_EDGE / 256, N_REL);  // 250 x 8 = 2000 CTAs
    edge_kernel<<<egrid, 256, EDGE_SMEM>>>(src, dst, ew, out);

    int n4 = out_size / 4;
    relu_kernel<<<1184, 256>>>((float4*)out, n4);
}